// round 2
// baseline (speedup 1.0000x reference)
#include <cuda_runtime.h>
#include <math.h>

// Problem constants
#define B_ 32
#define T_ 2048
#define D_ 512
#define H_ 512
#define G_ 2048   // 4*H

// Recurrence config
#define RCTAS 128
#define RTHREADS 256
#define UPC 4      // hidden units per CTA (128*4 = 512)
#define NROWS 16   // gate rows per CTA (4 gates * 4 units)

// ---------------------------------------------------------------------------
// Scratch (device globals; no runtime allocation allowed)
// ---------------------------------------------------------------------------
__device__ float g_xproj[(size_t)T_ * B_ * G_];   // 512 MB: [t][b][g]
__device__ float g_hbuf[2][H_ * B_];              // h double buffer, [k][b] layout
__device__ unsigned g_count = 0;                  // barrier arrival counter
__device__ unsigned g_gen   = 0;                  // barrier generation (monotone)

// ---------------------------------------------------------------------------
// Kernel 0: transpose h0 [b][k] -> g_hbuf[0] [k][b]
// ---------------------------------------------------------------------------
__global__ void init_h_kernel(const float* __restrict__ h0) {
    int idx = blockIdx.x * blockDim.x + threadIdx.x;   // 16384 threads
    if (idx >= B_ * H_) return;
    int b = idx >> 9;        // / H_
    int k = idx & (H_ - 1);
    g_hbuf[0][k * B_ + b] = h0[idx];
}

// ---------------------------------------------------------------------------
// Kernel 1: x_proj GEMM.  x_proj[t][b][g] = sum_d input[b][t][d]*W_ih[g][d]
//                                           + b_ih[g] + b_hh[g]
// Row index m = t*B + b  (matches x_proj row order directly).
// Tiles: 64x64, BK=16, 256 threads, 4x4 per-thread micro-tile. Pure fp32.
// ---------------------------------------------------------------------------
__global__ __launch_bounds__(256) void xproj_kernel(
    const float* __restrict__ input,
    const float* __restrict__ Wih,
    const float* __restrict__ bih,
    const float* __restrict__ bhh)
{
    __shared__ float As[16][64];   // [k][m]
    __shared__ float Bs[16][64];   // [k][n]

    int tid = threadIdx.x;
    int bn = blockIdx.x;           // 0..31
    int bm = blockIdx.y;           // 0..1023

    int tx = tid & 15;             // n-tile
    int ty = tid >> 4;             // m-tile

    int loadRow = tid >> 2;        // 0..63
    int loadK   = (tid & 3) * 4;   // 0,4,8,12

    int m0 = bm * 64;
    int n0 = bn * 64;

    // A row: global m -> (t, b), input addressed [b][t][d]
    int mg = m0 + loadRow;
    int t  = mg >> 5;              // / B_
    int b  = mg & 31;
    const float* aptr = input + ((size_t)(b * T_ + t)) * D_ + loadK;
    const float* bptr = Wih   + ((size_t)(n0 + loadRow)) * D_ + loadK;

    float acc[4][4] = {};

    for (int k0 = 0; k0 < D_; k0 += 16) {
        float4 av = *(const float4*)(aptr + k0);
        float4 bv = *(const float4*)(bptr + k0);
        As[loadK + 0][loadRow] = av.x;
        As[loadK + 1][loadRow] = av.y;
        As[loadK + 2][loadRow] = av.z;
        As[loadK + 3][loadRow] = av.w;
        Bs[loadK + 0][loadRow] = bv.x;
        Bs[loadK + 1][loadRow] = bv.y;
        Bs[loadK + 2][loadRow] = bv.z;
        Bs[loadK + 3][loadRow] = bv.w;
        __syncthreads();

        #pragma unroll
        for (int k = 0; k < 16; k++) {
            float4 a4 = *(const float4*)&As[k][ty * 4];
            float4 b4 = *(const float4*)&Bs[k][tx * 4];
            acc[0][0] = fmaf(a4.x, b4.x, acc[0][0]);
            acc[0][1] = fmaf(a4.x, b4.y, acc[0][1]);
            acc[0][2] = fmaf(a4.x, b4.z, acc[0][2]);
            acc[0][3] = fmaf(a4.x, b4.w, acc[0][3]);
            acc[1][0] = fmaf(a4.y, b4.x, acc[1][0]);
            acc[1][1] = fmaf(a4.y, b4.y, acc[1][1]);
            acc[1][2] = fmaf(a4.y, b4.z, acc[1][2]);
            acc[1][3] = fmaf(a4.y, b4.w, acc[1][3]);
            acc[2][0] = fmaf(a4.z, b4.x, acc[2][0]);
            acc[2][1] = fmaf(a4.z, b4.y, acc[2][1]);
            acc[2][2] = fmaf(a4.z, b4.z, acc[2][2]);
            acc[2][3] = fmaf(a4.z, b4.w, acc[2][3]);
            acc[3][0] = fmaf(a4.w, b4.x, acc[3][0]);
            acc[3][1] = fmaf(a4.w, b4.y, acc[3][1]);
            acc[3][2] = fmaf(a4.w, b4.z, acc[3][2]);
            acc[3][3] = fmaf(a4.w, b4.w, acc[3][3]);
        }
        __syncthreads();
    }

    float bias[4];
    #pragma unroll
    for (int j = 0; j < 4; j++) {
        int n = n0 + tx * 4 + j;
        bias[j] = __ldg(&bih[n]) + __ldg(&bhh[n]);
    }

    #pragma unroll
    for (int i = 0; i < 4; i++) {
        int m = m0 + ty * 4 + i;
        float4 v = make_float4(acc[i][0] + bias[0], acc[i][1] + bias[1],
                               acc[i][2] + bias[2], acc[i][3] + bias[3]);
        *(float4*)&g_xproj[(size_t)m * G_ + n0 + tx * 4] = v;
    }
}

// ---------------------------------------------------------------------------
// Kernel 2: persistent LSTM recurrence.
// 128 CTAs x 256 threads, all co-resident (1 CTA/SM). Each CTA owns 4 hidden
// units: 16 gate rows of W_hh in SMEM (transposed [k][r]), c-state in SMEM.
// Per step: load full h (64KB, L2, .cg to avoid stale L1) -> SMEM, compute
// 16x32 gate pre-activations, nonlinearity + state update, publish h slice,
// grid barrier (generation counter, wrap-safe compare).
// ---------------------------------------------------------------------------
extern "C" __global__ void __launch_bounds__(RTHREADS, 1) lstm_rec_kernel(
    const float* __restrict__ Whh,
    const float* __restrict__ c0,
    float* __restrict__ out)
{
    extern __shared__ float smem[];
    float* sWt   = smem;                    // 512*16 floats (32 KB)  [k][r]
    float* sHt   = sWt + 512 * NROWS;       // 512*32 floats (64 KB)  [k][b]
    float* sGate = sHt + 512 * B_;          // 16*32 floats           [r][b]
    float* sC    = sGate + NROWS * B_;      // 4*32 floats            [u][b]

    const int tid = threadIdx.x;
    const int cb  = blockIdx.x;
    const int u0  = cb * UPC;

    // Load W_hh slice, transposed into [k][r]
    for (int idx = tid; idx < NROWS * 512; idx += RTHREADS) {
        int r = idx >> 9;          // 0..15
        int k = idx & 511;
        int gate = r >> 2, ul = r & 3;
        int grow = gate * H_ + u0 + ul;
        sWt[k * NROWS + r] = __ldg(&Whh[(size_t)grow * H_ + k]);
    }
    // Init c state
    if (tid < UPC * B_) {
        int u = tid >> 5, b = tid & 31;
        sC[u * B_ + b] = __ldg(&c0[b * H_ + u0 + u]);
    }

    unsigned gen0 = *((volatile unsigned*)&g_gen);
    __syncthreads();

    const int r  = tid >> 4;       // 0..15 gate row
    const int bp = tid & 15;       // batch pair
    const int gate = r >> 2, ul = r & 3;
    const int grow = gate * H_ + u0 + ul;

    int cur = 0;
    for (int t = 0; t < T_; ++t) {
        // ---- load h(t) into SMEM (L2-coherent loads) ----
        const float4* gh = (const float4*)g_hbuf[cur];
        #pragma unroll 4
        for (int j = tid; j < (H_ * B_) / 4; j += RTHREADS) {
            ((float4*)sHt)[j] = __ldcg(gh + j);
        }
        __syncthreads();

        // ---- gate pre-activations: x_proj + h @ W_hh^T ----
        float acc0 = __ldg(&g_xproj[(size_t)(t * B_ + 2 * bp)     * G_ + grow]);
        float acc1 = __ldg(&g_xproj[(size_t)(t * B_ + 2 * bp + 1) * G_ + grow]);
        #pragma unroll 8
        for (int k = 0; k < H_; ++k) {
            float  w  = sWt[k * NROWS + r];
            float2 hv = *(const float2*)&sHt[k * B_ + 2 * bp];
            acc0 = fmaf(w, hv.x, acc0);
            acc1 = fmaf(w, hv.y, acc1);
        }
        sGate[r * B_ + 2 * bp]     = acc0;
        sGate[r * B_ + 2 * bp + 1] = acc1;
        __syncthreads();

        // ---- nonlinearity + state update (128 threads) ----
        int nxt = cur ^ 1;
        if (tid < UPC * B_) {
            int u = tid >> 5, b = tid & 31;
            float iv = sGate[(0  + u) * B_ + b];
            float fv = sGate[(4  + u) * B_ + b];
            float gv = sGate[(8  + u) * B_ + b];
            float ov = sGate[(12 + u) * B_ + b];
            iv = 1.0f / (1.0f + expf(-iv));
            fv = 1.0f / (1.0f + expf(-fv));
            gv = tanhf(gv);
            ov = 1.0f / (1.0f + expf(-ov));
            float c  = sC[u * B_ + b];
            float cn = fmaf(fv, c, iv * gv);
            float hn = ov * tanhf(cn);
            sC[u * B_ + b] = cn;
            g_hbuf[nxt][(u0 + u) * B_ + b] = hn;
            if (t == T_ - 1) {
                out[b * H_ + u0 + u]            = hn;   // h
                out[B_ * H_ + b * H_ + u0 + u]  = cn;   // c
            }
        }

        // ---- grid barrier ----
        __syncthreads();
        if (tid == 0) {
            __threadfence();
            unsigned a = atomicAdd(&g_count, 1u);
            if (a == (unsigned)(gridDim.x - 1)) {
                atomicExch(&g_count, 0u);
                __threadfence();
                atomicAdd(&g_gen, 1u);
            } else {
                unsigned target = gen0 + (unsigned)t + 1u;
                while ((int)(*((volatile unsigned*)&g_gen) - target) < 0) { }
                __threadfence();
            }
        }
        __syncthreads();
        cur = nxt;
    }
}

// ---------------------------------------------------------------------------
// Launch
// ---------------------------------------------------------------------------
extern "C" void kernel_launch(void* const* d_in, const int* in_sizes, int n_in,
                              void* d_out, int out_size)
{
    const float* input = (const float*)d_in[0];   // [B, T, D]
    const float* h0    = (const float*)d_in[1];   // [B, H]
    const float* c0    = (const float*)d_in[2];   // [B, H]
    const float* W_ih  = (const float*)d_in[3];   // [4H, D]
    const float* W_hh  = (const float*)d_in[4];   // [4H, H]
    const float* b_ih  = (const float*)d_in[5];   // [4H]
    const float* b_hh  = (const float*)d_in[6];   // [4H]
    float* out = (float*)d_out;                   // [2, B, H] (h then c)

    // Recurrence kernel needs ~98.5 KB dynamic SMEM
    static int rec_smem = (512 * NROWS + 512 * B_ + NROWS * B_ + UPC * B_) * (int)sizeof(float);
    cudaFuncSetAttribute(lstm_rec_kernel,
                         cudaFuncAttributeMaxDynamicSharedMemorySize, rec_smem);

    // 0) h0 -> [k][b] buffer
    init_h_kernel<<<(B_ * H_ + 255) / 256, 256>>>(h0);

    // 1) x_proj GEMM
    dim3 ggrid(G_ / 64, (B_ * T_) / 64);
    xproj_kernel<<<ggrid, 256>>>(input, W_ih, b_ih, b_hh);

    // 2) persistent recurrence
    lstm_rec_kernel<<<RCTAS, RTHREADS, rec_smem>>>(W_hh, c0, out);
}

// round 5
// speedup vs baseline: 1.0297x; 1.0297x over previous
#include <cuda_runtime.h>
#include <math.h>

// Problem constants
#define B_ 32
#define T_ 2048
#define D_ 512
#define H_ 512
#define G_ 2048   // 4*H

// Recurrence config
#define RCTAS 128
#define RTHREADS 256
#define UPC 4      // hidden units per CTA (128*4 = 512)
#define NROWS 16   // gate rows per CTA (4 gates * 4 units)

typedef unsigned long long ull;

// ---------------------------------------------------------------------------
// f32x2 packed helpers (sm_100+; conventions cancel: pack/FFMA2/unpack all
// use the same register-pair lane order)
// ---------------------------------------------------------------------------
__device__ __forceinline__ ull ffma2(ull a, ull b, ull c) {
    ull d;
    asm("fma.rn.f32x2 %0, %1, %2, %3;" : "=l"(d) : "l"(a), "l"(b), "l"(c));
    return d;
}
__device__ __forceinline__ ull dup_f32(float v) {
    ull d;
    asm("mov.b64 %0, {%1, %1};" : "=l"(d) : "f"(v));
    return d;
}
__device__ __forceinline__ ull pack_f32x2(float lo, float hi) {
    ull d;
    asm("mov.b64 %0, {%1, %2};" : "=l"(d) : "f"(lo), "f"(hi));
    return d;
}
__device__ __forceinline__ void unpack_f32x2(ull v, float& lo, float& hi) {
    asm("mov.b64 {%0, %1}, %2;" : "=f"(lo), "=f"(hi) : "l"(v));
}

// ---------------------------------------------------------------------------
// Scratch (device globals; no runtime allocation allowed)
// ---------------------------------------------------------------------------
__device__ float g_xproj[(size_t)T_ * B_ * G_];   // 512 MB: [t*B+b][g]
__device__ float g_hbuf[2][H_ * B_];              // h double buffer, [k][b]
__device__ unsigned g_count = 0;                  // barrier arrival counter (R2)
__device__ unsigned g_gen   = 0;                  // barrier generation (R2)

// ---------------------------------------------------------------------------
// Kernel 0: transpose h0 [b][k] -> g_hbuf[0] [k][b]   (R2-verbatim)
// ---------------------------------------------------------------------------
__global__ void init_h_kernel(const float* __restrict__ h0) {
    int idx = blockIdx.x * blockDim.x + threadIdx.x;
    if (idx >= B_ * H_) return;
    int b = idx >> 9;        // / H_
    int k = idx & (H_ - 1);
    g_hbuf[0][k * B_ + b] = h0[idx];
}

// ---------------------------------------------------------------------------
// Kernel 1: x_proj GEMM with f32x2.
// x_proj[(t*B+b)][g] = input[b][t][:] . W_ih[g][:] + b_ih[g] + b_hh[g]
// BM=128 x BN=64, BK=16, 256 threads, 8x4 micro-tile. A stored as duplicated
// (a,a) pairs -> n-paired FFMA2, no per-iteration packing.
// ---------------------------------------------------------------------------
__global__ __launch_bounds__(256) void xproj_kernel(
    const float* __restrict__ input,
    const float* __restrict__ Wih,
    const float* __restrict__ bih,
    const float* __restrict__ bhh)
{
    __shared__ ull   sAd[16 * 128];   // [k][m] duplicated pairs, 16 KB
    __shared__ float sBs[16 * 64];    // [k][n], 4 KB

    const int tid = threadIdx.x;
    const int bn = blockIdx.x;        // 0..31
    const int bm = blockIdx.y;        // 0..511

    const int tx = tid & 15;          // n = tx*4 .. +3
    const int ty = tid >> 4;          // m = ty*8 .. +7

    const int m0 = bm * 128;
    const int n0 = bn * 64;

    // A loader: 2 threads per m-row, 8 k each
    const int aRow = tid >> 1;            // 0..127
    const int aK   = (tid & 1) * 8;       // 0 or 8
    const int mg = m0 + aRow;
    const int t  = mg >> 5;
    const int b  = mg & 31;
    const float* aptr = input + ((size_t)(b * T_ + t)) * D_ + aK;

    // B loader: 4 threads per n-row, 4 k each
    const int bRow = tid >> 2;            // 0..63
    const int bK   = (tid & 3) * 4;
    const float* bptr = Wih + ((size_t)(n0 + bRow)) * D_ + bK;

    ull acc[8][2];
    #pragma unroll
    for (int i = 0; i < 8; i++) { acc[i][0] = 0ULL; acc[i][1] = 0ULL; }

    for (int k0 = 0; k0 < D_; k0 += 16) {
        float4 a0 = *(const float4*)(aptr + k0);
        float4 a1 = *(const float4*)(aptr + k0 + 4);
        float4 bv = *(const float4*)(bptr + k0);

        sAd[(aK + 0) * 128 + aRow] = dup_f32(a0.x);
        sAd[(aK + 1) * 128 + aRow] = dup_f32(a0.y);
        sAd[(aK + 2) * 128 + aRow] = dup_f32(a0.z);
        sAd[(aK + 3) * 128 + aRow] = dup_f32(a0.w);
        sAd[(aK + 4) * 128 + aRow] = dup_f32(a1.x);
        sAd[(aK + 5) * 128 + aRow] = dup_f32(a1.y);
        sAd[(aK + 6) * 128 + aRow] = dup_f32(a1.z);
        sAd[(aK + 7) * 128 + aRow] = dup_f32(a1.w);
        sBs[(bK + 0) * 64 + bRow] = bv.x;
        sBs[(bK + 1) * 64 + bRow] = bv.y;
        sBs[(bK + 2) * 64 + bRow] = bv.z;
        sBs[(bK + 3) * 64 + bRow] = bv.w;
        __syncthreads();

        #pragma unroll
        for (int k = 0; k < 16; k++) {
            ulonglong2 a01 = *(const ulonglong2*)&sAd[k * 128 + ty * 8];
            ulonglong2 a23 = *(const ulonglong2*)&sAd[k * 128 + ty * 8 + 2];
            ulonglong2 a45 = *(const ulonglong2*)&sAd[k * 128 + ty * 8 + 4];
            ulonglong2 a67 = *(const ulonglong2*)&sAd[k * 128 + ty * 8 + 6];
            ulonglong2 bb  = *(const ulonglong2*)&sBs[k * 64 + tx * 4];

            acc[0][0] = ffma2(a01.x, bb.x, acc[0][0]);
            acc[0][1] = ffma2(a01.x, bb.y, acc[0][1]);
            acc[1][0] = ffma2(a01.y, bb.x, acc[1][0]);
            acc[1][1] = ffma2(a01.y, bb.y, acc[1][1]);
            acc[2][0] = ffma2(a23.x, bb.x, acc[2][0]);
            acc[2][1] = ffma2(a23.x, bb.y, acc[2][1]);
            acc[3][0] = ffma2(a23.y, bb.x, acc[3][0]);
            acc[3][1] = ffma2(a23.y, bb.y, acc[3][1]);
            acc[4][0] = ffma2(a45.x, bb.x, acc[4][0]);
            acc[4][1] = ffma2(a45.x, bb.y, acc[4][1]);
            acc[5][0] = ffma2(a45.y, bb.x, acc[5][0]);
            acc[5][1] = ffma2(a45.y, bb.y, acc[5][1]);
            acc[6][0] = ffma2(a67.x, bb.x, acc[6][0]);
            acc[6][1] = ffma2(a67.x, bb.y, acc[6][1]);
            acc[7][0] = ffma2(a67.y, bb.x, acc[7][0]);
            acc[7][1] = ffma2(a67.y, bb.y, acc[7][1]);
        }
        __syncthreads();
    }

    float bias[4];
    #pragma unroll
    for (int j = 0; j < 4; j++) {
        int n = n0 + tx * 4 + j;
        bias[j] = __ldg(&bih[n]) + __ldg(&bhh[n]);
    }

    #pragma unroll
    for (int i = 0; i < 8; i++) {
        int m = m0 + ty * 8 + i;
        float v0, v1, v2, v3;
        unpack_f32x2(acc[i][0], v0, v1);
        unpack_f32x2(acc[i][1], v2, v3);
        float4 v = make_float4(v0 + bias[0], v1 + bias[1], v2 + bias[2], v3 + bias[3]);
        *(float4*)&g_xproj[(size_t)m * G_ + n0 + tx * 4] = v;
    }
}

// ---------------------------------------------------------------------------
// Kernel 2: persistent LSTM recurrence — R2 skeleton (PROVEN), minimal f32x2
// delta. Thread mapping, barrier, nonlinearity, h/c/out stores are R2-verbatim.
// Only change: W_hh slice stored as duplicated pairs in [r][k] layout and the
// inner dot uses ffma2 (1 packed FMA per k, LDS.128 w-fetch per 2 k).
// ---------------------------------------------------------------------------
extern "C" __global__ void __launch_bounds__(RTHREADS, 1) lstm_rec_kernel(
    const float* __restrict__ Whh,
    const float* __restrict__ c0,
    float* __restrict__ out)
{
    extern __shared__ char smem[];
    ull*   sWd   = (ull*)smem;                         // [16r][512k] dup pairs, 64 KB
    float* sH    = (float*)(smem + 65536);             // [512k][32b], 64 KB
    float* sGate = (float*)(smem + 131072);            // [16r][32b], 2 KB
    float* sC    = (float*)(smem + 131072 + 2048);     // [4u][32b]

    const int tid = threadIdx.x;
    const int cb  = blockIdx.x;
    const int u0  = cb * UPC;

    // Load W_hh slice as duplicated pairs, [r][k] layout
    for (int idx = tid; idx < NROWS * 512; idx += RTHREADS) {
        int r = idx >> 9;          // 0..15 (coalesced over k)
        int k = idx & 511;
        int gate = r >> 2, ul = r & 3;
        int grow = gate * H_ + u0 + ul;
        sWd[r * 512 + k] = dup_f32(__ldg(&Whh[(size_t)grow * H_ + k]));
    }
    if (tid < UPC * B_) {
        int u = tid >> 5, b = tid & 31;
        sC[u * B_ + b] = __ldg(&c0[b * H_ + u0 + u]);
    }

    unsigned gen0 = *((volatile unsigned*)&g_gen);
    __syncthreads();

    const int r  = tid >> 4;       // 0..15 gate row
    const int bp = tid & 15;       // batch pair
    const int gate = r >> 2, ul = r & 3;
    const int grow = gate * H_ + u0 + ul;
    const ull* wrow = &sWd[r * 512];

    int cur = 0;
    for (int t = 0; t < T_; ++t) {
        // ---- load h(t) into SMEM (L2-coherent loads) ----
        const float4* gh = (const float4*)g_hbuf[cur];
        #pragma unroll 4
        for (int j = tid; j < (H_ * B_) / 4; j += RTHREADS) {
            ((float4*)sH)[j] = __ldcg(gh + j);
        }
        __syncthreads();

        // ---- gate pre-activations: x_proj + h @ W_hh^T (packed pair) ----
        float xp0 = __ldg(&g_xproj[(size_t)(t * B_ + 2 * bp)     * G_ + grow]);
        float xp1 = __ldg(&g_xproj[(size_t)(t * B_ + 2 * bp + 1) * G_ + grow]);
        ull acc = pack_f32x2(xp0, xp1);   // lo = batch 2bp, hi = batch 2bp+1
        #pragma unroll 8
        for (int k = 0; k < H_; k += 2) {
            ulonglong2 w2 = *(const ulonglong2*)&wrow[k];          // w[k], w[k+1] dup
            ull hv0 = *(const ull*)&sH[k * B_ + 2 * bp];           // (h[k][2bp], h[k][2bp+1])
            ull hv1 = *(const ull*)&sH[(k + 1) * B_ + 2 * bp];
            acc = ffma2(w2.x, hv0, acc);
            acc = ffma2(w2.y, hv1, acc);
        }
        float acc0, acc1;
        unpack_f32x2(acc, acc0, acc1);
        sGate[r * B_ + 2 * bp]     = acc0;
        sGate[r * B_ + 2 * bp + 1] = acc1;
        __syncthreads();

        // ---- nonlinearity + state update (R2-verbatim, accurate math) ----
        int nxt = cur ^ 1;
        if (tid < UPC * B_) {
            int u = tid >> 5, b = tid & 31;
            float iv = sGate[(0  + u) * B_ + b];
            float fv = sGate[(4  + u) * B_ + b];
            float gv = sGate[(8  + u) * B_ + b];
            float ov = sGate[(12 + u) * B_ + b];
            iv = 1.0f / (1.0f + expf(-iv));
            fv = 1.0f / (1.0f + expf(-fv));
            gv = tanhf(gv);
            ov = 1.0f / (1.0f + expf(-ov));
            float c  = sC[u * B_ + b];
            float cn = fmaf(fv, c, iv * gv);
            float hn = ov * tanhf(cn);
            sC[u * B_ + b] = cn;
            g_hbuf[nxt][(u0 + u) * B_ + b] = hn;
            if (t == T_ - 1) {
                out[b * H_ + u0 + u]           = hn;   // h
                out[B_ * H_ + b * H_ + u0 + u] = cn;   // c
            }
        }

        // ---- grid barrier (R2-verbatim: generation counter) ----
        __syncthreads();
        if (tid == 0) {
            __threadfence();
            unsigned a = atomicAdd(&g_count, 1u);
            if (a == (unsigned)(gridDim.x - 1)) {
                atomicExch(&g_count, 0u);
                __threadfence();
                atomicAdd(&g_gen, 1u);
            } else {
                unsigned target = gen0 + (unsigned)t + 1u;
                while ((int)(*((volatile unsigned*)&g_gen) - target) < 0) { }
                __threadfence();
            }
        }
        __syncthreads();
        cur = nxt;
    }
}

// ---------------------------------------------------------------------------
// Launch
// ---------------------------------------------------------------------------
extern "C" void kernel_launch(void* const* d_in, const int* in_sizes, int n_in,
                              void* d_out, int out_size)
{
    const float* input = (const float*)d_in[0];   // [B, T, D]
    const float* h0    = (const float*)d_in[1];   // [B, H]
    const float* c0    = (const float*)d_in[2];   // [B, H]
    const float* W_ih  = (const float*)d_in[3];   // [4H, D]
    const float* W_hh  = (const float*)d_in[4];   // [4H, H]
    const float* b_ih  = (const float*)d_in[5];   // [4H]
    const float* b_hh  = (const float*)d_in[6];   // [4H]
    float* out = (float*)d_out;                   // [2, B, H]

    const int rec_smem = 65536 + 65536 + 2048 + 512;
    cudaFuncSetAttribute(lstm_rec_kernel,
                         cudaFuncAttributeMaxDynamicSharedMemorySize, rec_smem);

    // 0) h0 -> [k][b] buffer
    init_h_kernel<<<(B_ * H_ + 255) / 256, 256>>>(h0);

    // 1) x_proj GEMM (f32x2)
    dim3 ggrid(G_ / 64, (B_ * T_) / 128);
    xproj_kernel<<<ggrid, 256>>>(input, W_ih, b_ih, b_hh);

    // 2) persistent recurrence
    lstm_rec_kernel<<<RCTAS, RTHREADS, rec_smem>>>(W_hh, c0, out);
}

// round 7
// speedup vs baseline: 1.4664x; 1.4240x over previous
#include <cuda_runtime.h>
#include <math.h>

// Problem constants
#define B_ 32
#define T_ 2048
#define D_ 512
#define H_ 512
#define G_ 2048   // 4*H

// Recurrence config
#define RCTAS 128
#define RTHREADS 256
#define UPC 4      // hidden units per CTA (128*4 = 512)
#define NROWS 16   // gate rows per CTA (4 gates * 4 units)

typedef unsigned long long ull;

// ---------------------------------------------------------------------------
// f32x2 packed helpers (sm_100+)
// ---------------------------------------------------------------------------
__device__ __forceinline__ ull ffma2(ull a, ull b, ull c) {
    ull d;
    asm("fma.rn.f32x2 %0, %1, %2, %3;" : "=l"(d) : "l"(a), "l"(b), "l"(c));
    return d;
}
__device__ __forceinline__ ull dup_f32(float v) {
    ull d;
    asm("mov.b64 %0, {%1, %1};" : "=l"(d) : "f"(v));
    return d;
}
__device__ __forceinline__ void unpack_f32x2(ull v, float& lo, float& hi) {
    asm("mov.b64 {%0, %1}, %2;" : "=f"(lo), "=f"(hi) : "l"(v));
}

// ---------------------------------------------------------------------------
// Scratch (device globals; no runtime allocation allowed)
// ---------------------------------------------------------------------------
__device__ float g_xproj[(size_t)T_ * B_ * G_];   // 512 MB: [t*B+b][g]
__device__ float g_hbuf[2][H_ * B_];              // h double buffer, [k][b]
__device__ unsigned g_count = 0;                  // barrier arrival counter (PROVEN)
__device__ unsigned g_gen   = 0;                  // barrier generation (PROVEN)

// ---------------------------------------------------------------------------
// Kernel 0: transpose h0 [b][k] -> g_hbuf[0] [k][b]   (proven)
// ---------------------------------------------------------------------------
__global__ void init_h_kernel(const float* __restrict__ h0) {
    int idx = blockIdx.x * blockDim.x + threadIdx.x;
    if (idx >= B_ * H_) return;
    int b = idx >> 9;        // / H_
    int k = idx & (H_ - 1);
    g_hbuf[0][k * B_ + b] = h0[idx];
}

// ---------------------------------------------------------------------------
// Kernel 1: x_proj GEMM with f32x2 (R5-verbatim, PROVEN correct).
// ---------------------------------------------------------------------------
__global__ __launch_bounds__(256) void xproj_kernel(
    const float* __restrict__ input,
    const float* __restrict__ Wih,
    const float* __restrict__ bih,
    const float* __restrict__ bhh)
{
    __shared__ ull   sAd[16 * 128];   // [k][m] duplicated pairs, 16 KB
    __shared__ float sBs[16 * 64];    // [k][n], 4 KB

    const int tid = threadIdx.x;
    const int bn = blockIdx.x;        // 0..31
    const int bm = blockIdx.y;        // 0..511

    const int tx = tid & 15;          // n = tx*4 .. +3
    const int ty = tid >> 4;          // m = ty*8 .. +7

    const int m0 = bm * 128;
    const int n0 = bn * 64;

    const int aRow = tid >> 1;            // 0..127
    const int aK   = (tid & 1) * 8;       // 0 or 8
    const int mg = m0 + aRow;
    const int t  = mg >> 5;
    const int b  = mg & 31;
    const float* aptr = input + ((size_t)(b * T_ + t)) * D_ + aK;

    const int bRow = tid >> 2;            // 0..63
    const int bK   = (tid & 3) * 4;
    const float* bptr = Wih + ((size_t)(n0 + bRow)) * D_ + bK;

    ull acc[8][2];
    #pragma unroll
    for (int i = 0; i < 8; i++) { acc[i][0] = 0ULL; acc[i][1] = 0ULL; }

    for (int k0 = 0; k0 < D_; k0 += 16) {
        float4 a0 = *(const float4*)(aptr + k0);
        float4 a1 = *(const float4*)(aptr + k0 + 4);
        float4 bv = *(const float4*)(bptr + k0);

        sAd[(aK + 0) * 128 + aRow] = dup_f32(a0.x);
        sAd[(aK + 1) * 128 + aRow] = dup_f32(a0.y);
        sAd[(aK + 2) * 128 + aRow] = dup_f32(a0.z);
        sAd[(aK + 3) * 128 + aRow] = dup_f32(a0.w);
        sAd[(aK + 4) * 128 + aRow] = dup_f32(a1.x);
        sAd[(aK + 5) * 128 + aRow] = dup_f32(a1.y);
        sAd[(aK + 6) * 128 + aRow] = dup_f32(a1.z);
        sAd[(aK + 7) * 128 + aRow] = dup_f32(a1.w);
        sBs[(bK + 0) * 64 + bRow] = bv.x;
        sBs[(bK + 1) * 64 + bRow] = bv.y;
        sBs[(bK + 2) * 64 + bRow] = bv.z;
        sBs[(bK + 3) * 64 + bRow] = bv.w;
        __syncthreads();

        #pragma unroll
        for (int k = 0; k < 16; k++) {
            ulonglong2 a01 = *(const ulonglong2*)&sAd[k * 128 + ty * 8];
            ulonglong2 a23 = *(const ulonglong2*)&sAd[k * 128 + ty * 8 + 2];
            ulonglong2 a45 = *(const ulonglong2*)&sAd[k * 128 + ty * 8 + 4];
            ulonglong2 a67 = *(const ulonglong2*)&sAd[k * 128 + ty * 8 + 6];
            ulonglong2 bb  = *(const ulonglong2*)&sBs[k * 64 + tx * 4];

            acc[0][0] = ffma2(a01.x, bb.x, acc[0][0]);
            acc[0][1] = ffma2(a01.x, bb.y, acc[0][1]);
            acc[1][0] = ffma2(a01.y, bb.x, acc[1][0]);
            acc[1][1] = ffma2(a01.y, bb.y, acc[1][1]);
            acc[2][0] = ffma2(a23.x, bb.x, acc[2][0]);
            acc[2][1] = ffma2(a23.x, bb.y, acc[2][1]);
            acc[3][0] = ffma2(a23.y, bb.x, acc[3][0]);
            acc[3][1] = ffma2(a23.y, bb.y, acc[3][1]);
            acc[4][0] = ffma2(a45.x, bb.x, acc[4][0]);
            acc[4][1] = ffma2(a45.x, bb.y, acc[4][1]);
            acc[5][0] = ffma2(a45.y, bb.x, acc[5][0]);
            acc[5][1] = ffma2(a45.y, bb.y, acc[5][1]);
            acc[6][0] = ffma2(a67.x, bb.x, acc[6][0]);
            acc[6][1] = ffma2(a67.x, bb.y, acc[6][1]);
            acc[7][0] = ffma2(a67.y, bb.x, acc[7][0]);
            acc[7][1] = ffma2(a67.y, bb.y, acc[7][1]);
        }
        __syncthreads();
    }

    float bias[4];
    #pragma unroll
    for (int j = 0; j < 4; j++) {
        int n = n0 + tx * 4 + j;
        bias[j] = __ldg(&bih[n]) + __ldg(&bhh[n]);
    }

    #pragma unroll
    for (int i = 0; i < 8; i++) {
        int m = m0 + ty * 8 + i;
        float v0, v1, v2, v3;
        unpack_f32x2(acc[i][0], v0, v1);
        unpack_f32x2(acc[i][1], v2, v3);
        float4 v = make_float4(v0 + bias[0], v1 + bias[1], v2 + bias[2], v3 + bias[3]);
        *(float4*)&g_xproj[(size_t)m * G_ + n0 + tx * 4] = v;
    }
}

// ---------------------------------------------------------------------------
// Kernel 2: persistent LSTM recurrence.
// GEMM phase: register-tiled 4 rows x 4 batches x 64 k per thread (8-way
// k-split) -> 4x less SMEM crossbar traffic than the 1x2 mapping.
// Barrier: R2/R5-PROVEN generation counter. Accurate expf/tanhf.
// ---------------------------------------------------------------------------
extern "C" __global__ void __launch_bounds__(RTHREADS, 1) lstm_rec_kernel(
    const float* __restrict__ Whh,
    const float* __restrict__ c0,
    float* __restrict__ out)
{
    extern __shared__ char smem[];
    ull*   sWd   = (ull*)smem;                         // [512k][16r] dup pairs, 64 KB
    float* sH    = (float*)(smem + 65536);             // [512k][32b], 64 KB
    float* sPart = (float*)(smem + 131072);            // [8ks][16r][32b], 16 KB
    float* sGate = (float*)(smem + 131072 + 16384);    // [16r][32b], 2 KB
    float* sC    = (float*)(smem + 131072 + 16384 + 2048); // [4u][32b]

    const int tid = threadIdx.x;
    const int cb  = blockIdx.x;
    const int u0  = cb * UPC;

    // Load W_hh slice as duplicated pairs into sWd[k*16 + r]
    for (int idx = tid; idx < NROWS * 512; idx += RTHREADS) {
        int r = idx >> 9;          // 0..15 (coalesced over k)
        int k = idx & 511;
        int gate = r >> 2, ul = r & 3;
        int grow = gate * H_ + u0 + ul;
        sWd[k * NROWS + r] = dup_f32(__ldg(&Whh[(size_t)grow * H_ + k]));
    }
    if (tid < UPC * B_) {
        int u = tid >> 5, b = tid & 31;
        sC[u * B_ + b] = __ldg(&c0[b * H_ + u0 + u]);
    }

    // GEMM-phase thread mapping
    const int ks  = tid >> 5;          // 0..7 k-split
    const int pos = tid & 31;
    const int rg  = pos >> 3;          // 0..3: rows rg*4..+3
    const int bg  = pos & 7;           // 0..7: batches bg*4..+3
    const int r0  = rg * 4;
    const int b0  = bg * 4;
    const int kb  = ks * 64;

    // Reduce-phase mapping: outputs o = tid, tid+256 (o = r*32 + b)
    const int o0r = tid >> 5, o0b = tid & 31;
    const int o1r = (tid + 256) >> 5, o1b = tid & 31;
    const int o0grow = (o0r >> 2) * H_ + u0 + (o0r & 3);
    const int o1grow = (o1r >> 2) * H_ + u0 + (o1r & 3);

    unsigned gen0 = *((volatile unsigned*)&g_gen);
    __syncthreads();

    int cur = 0;
    for (int t = 0; t < T_; ++t) {
        // ---- prefetch x_proj for the reduce phase ----
        float xp0 = __ldg(&g_xproj[(size_t)(t * B_ + o0b) * G_ + o0grow]);
        float xp1 = __ldg(&g_xproj[(size_t)(t * B_ + o1b) * G_ + o1grow]);

        // ---- load h(t) into SMEM (L2-coherent) ----
        const float4* gh = (const float4*)g_hbuf[cur];
        #pragma unroll 4
        for (int j = tid; j < (H_ * B_) / 4; j += RTHREADS) {
            ((float4*)sH)[j] = __ldcg(gh + j);
        }
        __syncthreads();

        // ---- gate GEMM: 4 rows x 4 batches, k in [kb, kb+64) ----
        ull acc[4][2];
        #pragma unroll
        for (int i = 0; i < 4; i++) { acc[i][0] = 0ULL; acc[i][1] = 0ULL; }

        #pragma unroll 8
        for (int kk = 0; kk < 64; ++kk) {
            int k = kb + kk;
            ulonglong2 w01 = *(const ulonglong2*)&sWd[k * NROWS + r0];
            ulonglong2 w23 = *(const ulonglong2*)&sWd[k * NROWS + r0 + 2];
            ulonglong2 hv  = *(const ulonglong2*)&sH[k * B_ + b0];
            acc[0][0] = ffma2(w01.x, hv.x, acc[0][0]);
            acc[0][1] = ffma2(w01.x, hv.y, acc[0][1]);
            acc[1][0] = ffma2(w01.y, hv.x, acc[1][0]);
            acc[1][1] = ffma2(w01.y, hv.y, acc[1][1]);
            acc[2][0] = ffma2(w23.x, hv.x, acc[2][0]);
            acc[2][1] = ffma2(w23.x, hv.y, acc[2][1]);
            acc[3][0] = ffma2(w23.y, hv.x, acc[3][0]);
            acc[3][1] = ffma2(w23.y, hv.y, acc[3][1]);
        }
        #pragma unroll
        for (int i = 0; i < 4; i++) {
            int base = ks * 512 + (r0 + i) * B_ + b0;
            *(ull*)&sPart[base]     = acc[i][0];
            *(ull*)&sPart[base + 2] = acc[i][1];
        }
        __syncthreads();

        // ---- reduce k-splits + add x_proj ----
        {
            float s0 = xp0, s1 = xp1;
            #pragma unroll
            for (int s = 0; s < 8; s++) {
                s0 += sPart[s * 512 + tid];
                s1 += sPart[s * 512 + tid + 256];
            }
            sGate[tid] = s0;
            sGate[tid + 256] = s1;
        }
        __syncthreads();

        // ---- nonlinearity + state update (accurate math, PROVEN) ----
        int nxt = cur ^ 1;
        if (tid < UPC * B_) {
            int u = tid >> 5, b = tid & 31;
            float iv = sGate[(0  + u) * B_ + b];
            float fv = sGate[(4  + u) * B_ + b];
            float gv = sGate[(8  + u) * B_ + b];
            float ov = sGate[(12 + u) * B_ + b];
            iv = 1.0f / (1.0f + expf(-iv));
            fv = 1.0f / (1.0f + expf(-fv));
            gv = tanhf(gv);
            ov = 1.0f / (1.0f + expf(-ov));
            float c  = sC[u * B_ + b];
            float cn = fmaf(fv, c, iv * gv);
            float hn = ov * tanhf(cn);
            sC[u * B_ + b] = cn;
            g_hbuf[nxt][(u0 + u) * B_ + b] = hn;
            if (t == T_ - 1) {
                out[b * H_ + u0 + u]           = hn;   // h
                out[B_ * H_ + b * H_ + u0 + u] = cn;   // c
            }
        }

        // ---- grid barrier (R2/R5-PROVEN generation counter, verbatim) ----
        __syncthreads();
        if (tid == 0) {
            __threadfence();
            unsigned a = atomicAdd(&g_count, 1u);
            if (a == (unsigned)(gridDim.x - 1)) {
                atomicExch(&g_count, 0u);
                __threadfence();
                atomicAdd(&g_gen, 1u);
            } else {
                unsigned target = gen0 + (unsigned)t + 1u;
                while ((int)(*((volatile unsigned*)&g_gen) - target) < 0) { }
                __threadfence();
            }
        }
        __syncthreads();
        cur = nxt;
    }
}

// ---------------------------------------------------------------------------
// Launch
// ---------------------------------------------------------------------------
extern "C" void kernel_launch(void* const* d_in, const int* in_sizes, int n_in,
                              void* d_out, int out_size)
{
    const float* input = (const float*)d_in[0];   // [B, T, D]
    const float* h0    = (const float*)d_in[1];   // [B, H]
    const float* c0    = (const float*)d_in[2];   // [B, H]
    const float* W_ih  = (const float*)d_in[3];   // [4H, D]
    const float* W_hh  = (const float*)d_in[4];   // [4H, H]
    const float* b_ih  = (const float*)d_in[5];   // [4H]
    const float* b_hh  = (const float*)d_in[6];   // [4H]
    float* out = (float*)d_out;                   // [2, B, H]

    const int rec_smem = 65536 + 65536 + 16384 + 2048 + 512;
    cudaFuncSetAttribute(lstm_rec_kernel,
                         cudaFuncAttributeMaxDynamicSharedMemorySize, rec_smem);

    // 0) h0 -> [k][b] buffer
    init_h_kernel<<<(B_ * H_ + 255) / 256, 256>>>(h0);

    // 1) x_proj GEMM (f32x2)
    dim3 ggrid(G_ / 64, (B_ * T_) / 128);
    xproj_kernel<<<ggrid, 256>>>(input, W_ih, b_ih, b_hh);

    // 2) persistent recurrence
    lstm_rec_kernel<<<RCTAS, RTHREADS, rec_smem>>>(W_hh, c0, out);
}

// round 8
// speedup vs baseline: 1.7675x; 1.2054x over previous
#include <cuda_runtime.h>
#include <math.h>

// Problem constants
#define B_ 32
#define T_ 2048
#define D_ 512
#define H_ 512
#define G_ 2048   // 4*H

// Recurrence config: 4 independent groups x 32 CTAs; group owns 8 batches.
#define GROUPS 4
#define CPG 32     // CTAs per group
#define BPG 8      // batches per group
#define UPC2 16    // hidden units per CTA
#define LROWS 64   // local gate rows per CTA (4 gates * 16 units)
#define RCTAS (GROUPS * CPG)
#define RTHREADS 256

typedef unsigned long long ull;

// ---------------------------------------------------------------------------
// f32x2 packed helpers
// ---------------------------------------------------------------------------
__device__ __forceinline__ ull ffma2(ull a, ull b, ull c) {
    ull d;
    asm("fma.rn.f32x2 %0, %1, %2, %3;" : "=l"(d) : "l"(a), "l"(b), "l"(c));
    return d;
}
__device__ __forceinline__ ull dup_f32(float v) {
    ull d;
    asm("mov.b64 %0, {%1, %1};" : "=l"(d) : "f"(v));
    return d;
}
__device__ __forceinline__ void unpack_f32x2(ull v, float& lo, float& hi) {
    asm("mov.b64 {%0, %1}, %2;" : "=f"(lo), "=f"(hi) : "l"(v));
}

// ---------------------------------------------------------------------------
// Scratch (device globals)
// ---------------------------------------------------------------------------
__device__ float g_xproj[(size_t)T_ * B_ * G_];     // [t*B+b][g]
__device__ float g_hb[GROUPS][2][H_ * BPG];         // per-group h, [k*8+b]
__device__ unsigned g_cnt[GROUPS * 64];             // per-group arrival (256B stride)
__device__ unsigned g_genA[GROUPS * 64];            // per-group generation

// ---------------------------------------------------------------------------
// Kernel 0: h0 [b][k] -> per-group buffers [k*8 + b_local]
// ---------------------------------------------------------------------------
__global__ void init_h_kernel(const float* __restrict__ h0) {
    int idx = blockIdx.x * blockDim.x + threadIdx.x;
    if (idx >= B_ * H_) return;
    int b = idx >> 9;        // global batch
    int k = idx & (H_ - 1);
    g_hb[b >> 3][0][k * BPG + (b & 7)] = h0[idx];
}

// ---------------------------------------------------------------------------
// Kernel 1: x_proj GEMM with f32x2 (R5/R6-verbatim, PROVEN correct).
// ---------------------------------------------------------------------------
__global__ __launch_bounds__(256) void xproj_kernel(
    const float* __restrict__ input,
    const float* __restrict__ Wih,
    const float* __restrict__ bih,
    const float* __restrict__ bhh)
{
    __shared__ ull   sAd[16 * 128];   // [k][m] duplicated pairs
    __shared__ float sBs[16 * 64];    // [k][n]

    const int tid = threadIdx.x;
    const int bn = blockIdx.x;
    const int bm = blockIdx.y;

    const int tx = tid & 15;
    const int ty = tid >> 4;

    const int m0 = bm * 128;
    const int n0 = bn * 64;

    const int aRow = tid >> 1;
    const int aK   = (tid & 1) * 8;
    const int mg = m0 + aRow;
    const int t  = mg >> 5;
    const int b  = mg & 31;
    const float* aptr = input + ((size_t)(b * T_ + t)) * D_ + aK;

    const int bRow = tid >> 2;
    const int bK   = (tid & 3) * 4;
    const float* bptr = Wih + ((size_t)(n0 + bRow)) * D_ + bK;

    ull acc[8][2];
    #pragma unroll
    for (int i = 0; i < 8; i++) { acc[i][0] = 0ULL; acc[i][1] = 0ULL; }

    for (int k0 = 0; k0 < D_; k0 += 16) {
        float4 a0 = *(const float4*)(aptr + k0);
        float4 a1 = *(const float4*)(aptr + k0 + 4);
        float4 bv = *(const float4*)(bptr + k0);

        sAd[(aK + 0) * 128 + aRow] = dup_f32(a0.x);
        sAd[(aK + 1) * 128 + aRow] = dup_f32(a0.y);
        sAd[(aK + 2) * 128 + aRow] = dup_f32(a0.z);
        sAd[(aK + 3) * 128 + aRow] = dup_f32(a0.w);
        sAd[(aK + 4) * 128 + aRow] = dup_f32(a1.x);
        sAd[(aK + 5) * 128 + aRow] = dup_f32(a1.y);
        sAd[(aK + 6) * 128 + aRow] = dup_f32(a1.z);
        sAd[(aK + 7) * 128 + aRow] = dup_f32(a1.w);
        sBs[(bK + 0) * 64 + bRow] = bv.x;
        sBs[(bK + 1) * 64 + bRow] = bv.y;
        sBs[(bK + 2) * 64 + bRow] = bv.z;
        sBs[(bK + 3) * 64 + bRow] = bv.w;
        __syncthreads();

        #pragma unroll
        for (int k = 0; k < 16; k++) {
            ulonglong2 a01 = *(const ulonglong2*)&sAd[k * 128 + ty * 8];
            ulonglong2 a23 = *(const ulonglong2*)&sAd[k * 128 + ty * 8 + 2];
            ulonglong2 a45 = *(const ulonglong2*)&sAd[k * 128 + ty * 8 + 4];
            ulonglong2 a67 = *(const ulonglong2*)&sAd[k * 128 + ty * 8 + 6];
            ulonglong2 bb  = *(const ulonglong2*)&sBs[k * 64 + tx * 4];

            acc[0][0] = ffma2(a01.x, bb.x, acc[0][0]);
            acc[0][1] = ffma2(a01.x, bb.y, acc[0][1]);
            acc[1][0] = ffma2(a01.y, bb.x, acc[1][0]);
            acc[1][1] = ffma2(a01.y, bb.y, acc[1][1]);
            acc[2][0] = ffma2(a23.x, bb.x, acc[2][0]);
            acc[2][1] = ffma2(a23.x, bb.y, acc[2][1]);
            acc[3][0] = ffma2(a23.y, bb.x, acc[3][0]);
            acc[3][1] = ffma2(a23.y, bb.y, acc[3][1]);
            acc[4][0] = ffma2(a45.x, bb.x, acc[4][0]);
            acc[4][1] = ffma2(a45.x, bb.y, acc[4][1]);
            acc[5][0] = ffma2(a45.y, bb.x, acc[5][0]);
            acc[5][1] = ffma2(a45.y, bb.y, acc[5][1]);
            acc[6][0] = ffma2(a67.x, bb.x, acc[6][0]);
            acc[6][1] = ffma2(a67.x, bb.y, acc[6][1]);
            acc[7][0] = ffma2(a67.y, bb.x, acc[7][0]);
            acc[7][1] = ffma2(a67.y, bb.y, acc[7][1]);
        }
        __syncthreads();
    }

    float bias[4];
    #pragma unroll
    for (int j = 0; j < 4; j++) {
        int n = n0 + tx * 4 + j;
        bias[j] = __ldg(&bih[n]) + __ldg(&bhh[n]);
    }

    #pragma unroll
    for (int i = 0; i < 8; i++) {
        int m = m0 + ty * 8 + i;
        float v0, v1, v2, v3;
        unpack_f32x2(acc[i][0], v0, v1);
        unpack_f32x2(acc[i][1], v2, v3);
        float4 v = make_float4(v0 + bias[0], v1 + bias[1], v2 + bias[2], v3 + bias[3]);
        *(float4*)&g_xproj[(size_t)m * G_ + n0 + tx * 4] = v;
    }
}

// ---------------------------------------------------------------------------
// Kernel 2: persistent LSTM recurrence, 4 independent 32-CTA groups.
// CTA: 64 gate rows (16 units x 4 gates) x 8 batches, W in [k][64r] SMEM
// (row-pair f32x2 packing, no duplication), h pre-duplicated (32 KB).
// GEMM: thread tile 8 rows x 4 batches, 16-way k-split (kchunk 32).
// Barrier: PROVEN generation counter, per group.
// ---------------------------------------------------------------------------
extern "C" __global__ void __launch_bounds__(RTHREADS, 1) lstm_rec_kernel(
    const float* __restrict__ Whh,
    const float* __restrict__ c0,
    float* __restrict__ out)
{
    extern __shared__ char smem[];
    float* sW     = (float*)smem;                        // [512k][64r], 128 KB
    ull*   sHd    = (ull*)(smem + 131072);               // [512k][8b] dup'd, 32 KB
    float* sPartF = (float*)(smem + 131072 + 32768);     // [16ks][8b][64r], 32 KB
    ull*   sPartU = (ull*)sPartF;                        // [16ks][8b][32rp]
    float* sGate  = (float*)(smem + 131072 + 65536);     // [8b][64r], 2 KB
    float* sC     = (float*)(smem + 131072 + 65536 + 2048); // [16ul][8b]

    const int tid = threadIdx.x;
    const int cta = blockIdx.x;
    const int g   = cta >> 5;          // group 0..3
    const int cg  = cta & 31;          // CTA in group
    const int u0  = cg * UPC2;         // first unit

    // ---- load W_hh slice: sW[k*64 + r] = Whh[(gate*512 + u0 + ul)][k] ----
    for (int idx = tid; idx < LROWS * 512; idx += RTHREADS) {
        int r = idx >> 9;              // 0..63
        int k = idx & 511;
        int gate = r >> 4, ul = r & 15;
        int grow = gate * H_ + u0 + ul;
        sW[k * LROWS + r] = __ldg(&Whh[(size_t)grow * H_ + k]);
    }
    // ---- init c state: sC[ul*8 + b] ----
    if (tid < UPC2 * BPG) {
        int ul = tid >> 3, b = tid & 7;
        int bglob = g * BPG + b;
        sC[tid] = __ldg(&c0[bglob * H_ + u0 + ul]);
    }

    // GEMM-phase mapping: 16 k-splits x (8 row-groups x 2 batch-groups)
    const int ks  = tid >> 4;          // 0..15, k in [ks*32, ks*32+32)
    const int pos = tid & 15;
    const int rg  = pos >> 1;          // 0..7 -> rows rg*8 .. +7 (4 row-pairs)
    const int bg  = pos & 1;           // 0..1 -> batches bg*4 .. +3
    const int r0  = rg * 8;
    const int b0  = bg * 4;
    const int kb  = ks * 32;

    // Reduce-phase mapping: outputs o = tid, tid+256; o = b*64 + r
    const int o0 = tid, o1 = tid + 256;
    const int o0b = o0 >> 6, o0r = o0 & 63;
    const int o1b = o1 >> 6, o1r = o1 & 63;
    const int o0grow = (o0r >> 4) * H_ + u0 + (o0r & 15);
    const int o1grow = (o1r >> 4) * H_ + u0 + (o1r & 15);
    const int o0bg = g * BPG + o0b;
    const int o1bg = g * BPG + o1b;

    unsigned gen0 = *((volatile unsigned*)&g_genA[g * 64]);
    __syncthreads();

    int cur = 0;
    for (int t = 0; t < T_; ++t) {
        // ---- prefetch x_proj for reduce ----
        float xp0 = __ldg(&g_xproj[(size_t)(t * B_ + o0bg) * G_ + o0grow]);
        float xp1 = __ldg(&g_xproj[(size_t)(t * B_ + o1bg) * G_ + o1grow]);

        // ---- load group h (16 KB) and duplicate into sHd ----
        {
            const float4* gh = (const float4*)g_hb[g][cur];
            #pragma unroll
            for (int j = tid; j < (H_ * BPG) / 4; j += RTHREADS) {
                float4 v = __ldcg(gh + j);
                ulonglong2 d0, d1;
                d0.x = dup_f32(v.x); d0.y = dup_f32(v.y);
                d1.x = dup_f32(v.z); d1.y = dup_f32(v.w);
                *(ulonglong2*)&sHd[j * 4]     = d0;
                *(ulonglong2*)&sHd[j * 4 + 2] = d1;
            }
        }
        __syncthreads();

        // ---- gate GEMM: 4 row-pairs x 4 batches, k in [kb, kb+32) ----
        ull acc[4][4];   // [row-pair][batch]
        #pragma unroll
        for (int i = 0; i < 4; i++)
            #pragma unroll
            for (int j = 0; j < 4; j++) acc[i][j] = 0ULL;

        #pragma unroll 8
        for (int kk = 0; kk < 32; ++kk) {
            int k = kb + kk;
            ulonglong2 wA = *(const ulonglong2*)&sW[k * LROWS + r0];      // pairs (r0,r0+1),(r0+2,r0+3)
            ulonglong2 wB = *(const ulonglong2*)&sW[k * LROWS + r0 + 4];  // pairs (r0+4..7)
            ulonglong2 h01 = *(const ulonglong2*)&sHd[k * BPG + b0];      // dup b0, b0+1
            ulonglong2 h23 = *(const ulonglong2*)&sHd[k * BPG + b0 + 2];  // dup b0+2, b0+3
            acc[0][0] = ffma2(wA.x, h01.x, acc[0][0]);
            acc[0][1] = ffma2(wA.x, h01.y, acc[0][1]);
            acc[0][2] = ffma2(wA.x, h23.x, acc[0][2]);
            acc[0][3] = ffma2(wA.x, h23.y, acc[0][3]);
            acc[1][0] = ffma2(wA.y, h01.x, acc[1][0]);
            acc[1][1] = ffma2(wA.y, h01.y, acc[1][1]);
            acc[1][2] = ffma2(wA.y, h23.x, acc[1][2]);
            acc[1][3] = ffma2(wA.y, h23.y, acc[1][3]);
            acc[2][0] = ffma2(wB.x, h01.x, acc[2][0]);
            acc[2][1] = ffma2(wB.x, h01.y, acc[2][1]);
            acc[2][2] = ffma2(wB.x, h23.x, acc[2][2]);
            acc[2][3] = ffma2(wB.x, h23.y, acc[2][3]);
            acc[3][0] = ffma2(wB.y, h01.x, acc[3][0]);
            acc[3][1] = ffma2(wB.y, h01.y, acc[3][1]);
            acc[3][2] = ffma2(wB.y, h23.x, acc[3][2]);
            acc[3][3] = ffma2(wB.y, h23.y, acc[3][3]);
        }
        // store partials: sPartU[ks][b][rp], rp = r/2
        #pragma unroll
        for (int j = 0; j < 4; j++) {
            int base = ks * 256 + (b0 + j) * 32 + (r0 >> 1);
            ulonglong2 p0, p1;
            p0.x = acc[0][j]; p0.y = acc[1][j];
            p1.x = acc[2][j]; p1.y = acc[3][j];
            *(ulonglong2*)&sPartU[base]     = p0;
            *(ulonglong2*)&sPartU[base + 2] = p1;
        }
        __syncthreads();

        // ---- reduce 16 k-splits + add x_proj ----
        {
            float s0 = xp0, s1 = xp1;
            #pragma unroll
            for (int s = 0; s < 16; s++) {
                s0 += sPartF[s * 512 + o0];
                s1 += sPartF[s * 512 + o1];
            }
            sGate[o0] = s0;
            sGate[o1] = s1;
        }
        __syncthreads();

        // ---- nonlinearity + state update (accurate math) ----
        int nxt = cur ^ 1;
        if (tid < UPC2 * BPG) {
            int ul = tid >> 3, b = tid & 7;
            float iv = sGate[b * 64 +  0 + ul];
            float fv = sGate[b * 64 + 16 + ul];
            float gv = sGate[b * 64 + 32 + ul];
            float ov = sGate[b * 64 + 48 + ul];
            iv = 1.0f / (1.0f + expf(-iv));
            fv = 1.0f / (1.0f + expf(-fv));
            gv = tanhf(gv);
            ov = 1.0f / (1.0f + expf(-ov));
            float c  = sC[tid];
            float cn = fmaf(fv, c, iv * gv);
            float hn = ov * tanhf(cn);
            sC[tid] = cn;
            g_hb[g][nxt][(u0 + ul) * BPG + b] = hn;
            if (t == T_ - 1) {
                int bglob = g * BPG + b;
                out[bglob * H_ + u0 + ul]           = hn;   // h
                out[B_ * H_ + bglob * H_ + u0 + ul] = cn;   // c
            }
        }

        // ---- per-group grid barrier (PROVEN generation counter) ----
        __syncthreads();
        if (tid == 0) {
            __threadfence();
            unsigned a = atomicAdd(&g_cnt[g * 64], 1u);
            if (a == (unsigned)(CPG - 1)) {
                atomicExch(&g_cnt[g * 64], 0u);
                __threadfence();
                atomicAdd(&g_genA[g * 64], 1u);
            } else {
                unsigned target = gen0 + (unsigned)t + 1u;
                while ((int)(*((volatile unsigned*)&g_genA[g * 64]) - target) < 0) { }
                __threadfence();
            }
        }
        __syncthreads();
        cur = nxt;
    }
}

// ---------------------------------------------------------------------------
// Launch
// ---------------------------------------------------------------------------
extern "C" void kernel_launch(void* const* d_in, const int* in_sizes, int n_in,
                              void* d_out, int out_size)
{
    const float* input = (const float*)d_in[0];   // [B, T, D]
    const float* h0    = (const float*)d_in[1];   // [B, H]
    const float* c0    = (const float*)d_in[2];   // [B, H]
    const float* W_ih  = (const float*)d_in[3];   // [4H, D]
    const float* W_hh  = (const float*)d_in[4];   // [4H, H]
    const float* b_ih  = (const float*)d_in[5];   // [4H]
    const float* b_hh  = (const float*)d_in[6];   // [4H]
    float* out = (float*)d_out;                   // [2, B, H]

    const int rec_smem = 131072 + 32768 + 32768 + 2048 + 512;   // 199168 B
    cudaFuncSetAttribute(lstm_rec_kernel,
                         cudaFuncAttributeMaxDynamicSharedMemorySize, rec_smem);

    // 0) h0 -> per-group buffers
    init_h_kernel<<<(B_ * H_ + 255) / 256, 256>>>(h0);

    // 1) x_proj GEMM (f32x2, proven)
    dim3 ggrid(G_ / 64, (B_ * T_) / 128);
    xproj_kernel<<<ggrid, 256>>>(input, W_ih, b_ih, b_hh);

    // 2) persistent recurrence (4 independent groups)
    lstm_rec_kernel<<<RCTAS, RTHREADS, rec_smem>>>(W_hh, c0, out);
}